// round 5
// baseline (speedup 1.0000x reference)
#include <cuda_runtime.h>
#include <math.h>

#define NMAX 150000
#define EMAX 150000
#define ITERS_T 31
#define HMAX 65536

// ---------------- device scratch (static allocations only) ----------------
__device__ float g_c[NMAX * 128];       // cell state c (h lives in d_out)
__device__ float g_xh[HMAX * 384];      // per-has-input-node child_h accum (zero-init, self-cleaning)
__device__ float g_xfc[HMAX * 384];     // per-has-input-node f*c accum
__device__ int g_mnode[NMAX];           // has-input node ids, grouped by iteration
__device__ int g_xslot[NMAX];           // node -> dense accumulation slot
__device__ int g_hasin[NMAX];
__device__ int g_ep[EMAX], g_ec[EMAX], g_es[EMAX];   // mattering edges grouped by iter
__device__ int g_ecnt[ITERS_T + 1], g_ncnt[ITERS_T + 1];
__device__ int g_eoff[ITERS_T + 2], g_noff[ITERS_T + 2];
__device__ int g_ecur[ITERS_T + 1], g_ncur[ITERS_T + 1];

// ---------------- prep ----------------
__global__ void k_init(int n) {
    int i = blockIdx.x * blockDim.x + threadIdx.x;
    if (i < n) g_hasin[i] = 0;
    if (i <= ITERS_T) { g_ecnt[i] = 0; g_ncnt[i] = 0; g_ecur[i] = 0; g_ncur[i] = 0; }
}

// NOTE: adjacency / node_order / edge_order arrive as int32 (JAX x64 disabled).
__device__ __forceinline__ bool edge_matters(
    const int* __restrict__ adj, const int* __restrict__ no,
    const int* __restrict__ eo, int n, int i,
    int& sp, int& sc, int& slot, int& ti)
{
    int p = adj[3 * i], c = adj[3 * i + 1];
    if (!(p >= 0 && p < n && c >= 0 && c < n)) return false;   // valid
    int t = eo[i];
    if (t < 0 || t >= ITERS_T) return false;
    sp = p; sc = c;
    if (no[sp] != t) return false;       // parent must update at this iteration
    if (!(no[sc] < t)) return false;     // child h/c still zero otherwise -> no-op
    int s = adj[3 * i + 2] + 1;
    slot = s < 0 ? 0 : (s > 2 ? 2 : s);
    ti = t;
    return true;
}

__global__ void k_count(const int* __restrict__ adj, const int* __restrict__ no,
                        const int* __restrict__ eo, int n, int e) {
    int i = blockIdx.x * blockDim.x + threadIdx.x;
    if (i >= e) return;
    int sp, sc, slot, ti;
    if (!edge_matters(adj, no, eo, n, i, sp, sc, slot, ti)) return;
    atomicAdd(&g_ecnt[ti], 1);
    if (atomicExch(&g_hasin[sp], 1) == 0) atomicAdd(&g_ncnt[ti], 1);
}

__global__ void k_scan() {
    if (threadIdx.x == 0 && blockIdx.x == 0) {
        int se = 0, sn = 0;
        for (int t = 0; t < ITERS_T; t++) {
            g_eoff[t] = se; se += g_ecnt[t];
            g_noff[t] = sn; sn += g_ncnt[t];
        }
        g_eoff[ITERS_T] = se; g_noff[ITERS_T] = sn;
    }
}

__global__ void k_node_scatter(const int* __restrict__ no, int n) {
    int i = blockIdx.x * blockDim.x + threadIdx.x;
    if (i >= n) return;
    if (!g_hasin[i]) return;
    int t = no[i];
    if (t < 0 || t >= ITERS_T) return;
    int pos = g_noff[t] + atomicAdd(&g_ncur[t], 1);
    g_mnode[pos] = i;
    g_xslot[i] = pos < HMAX ? pos : HMAX - 1;
}

__global__ void k_edge_scatter(const int* __restrict__ adj, const int* __restrict__ no,
                               const int* __restrict__ eo, int n, int e) {
    int i = blockIdx.x * blockDim.x + threadIdx.x;
    if (i >= e) return;
    int sp, sc, slot, ti;
    if (!edge_matters(adj, no, eo, n, i, sp, sc, slot, ti)) return;
    int pos = g_eoff[ti] + atomicAdd(&g_ecur[ti], 1);
    g_ep[pos] = sp; g_ec[pos] = sc; g_es[pos] = slot;
}

// ---------------- simple pass v2: register-tiled SGEMM + fused epilogue --------------
// Block tile: M=128 nodes, 32 cols of each of 3 gates (N_eff=96), K=128 in 16 chunks of 8.
// 256 threads; each thread computes 8 rows x (3 gates x 2 cols) = 48 outputs.
// iou = forest @ W_iou + b_iou ; c = sig(i)*tanh(u) + b_c ; h = sig(o)*tanh(c)
__global__ void __launch_bounds__(256) k_simple(
    const float* __restrict__ forest, const float* __restrict__ W_iou,
    const float* __restrict__ b_iou, const float* __restrict__ b_c,
    float* __restrict__ hout, int n)
{
    __shared__ float As[8][132];     // transposed A chunk, padded row
    __shared__ float Bs[8][96];      // [k][g*32+jj]
    int tid = threadIdx.x;
    int bm = blockIdx.x, bj = blockIdx.y;
    int tx = tid & 15;               // 2 cols per gate: jj = tx*2
    int ty = tid >> 4;               // 8 rows: m = ty*8 + i

    // A load mapping: each thread one float4
    int arow = tid >> 1;
    int acol = (tid & 1) * 4;
    int grow = bm * 128 + arow; if (grow >= n) grow = n - 1;
    const float* aptr = forest + (size_t)grow * 128 + acol;

    float acc[8][3][2];
#pragma unroll
    for (int i = 0; i < 8; i++)
#pragma unroll
        for (int g = 0; g < 3; g++) { acc[i][g][0] = 0.f; acc[i][g][1] = 0.f; }

    for (int kc = 0; kc < 16; kc++) {
        float4 av = *(const float4*)(aptr + kc * 8);
        As[acol + 0][arow] = av.x;
        As[acol + 1][arow] = av.y;
        As[acol + 2][arow] = av.z;
        As[acol + 3][arow] = av.w;
#pragma unroll
        for (int s = 0; s < 3; s++) {
            int idx = s * 256 + tid;           // 0..767 covers 8x96
            int kk = idx / 96, c = idx - kk * 96;
            int g = c >> 5, jj = c & 31;
            Bs[kk][c] = W_iou[(kc * 8 + kk) * 384 + g * 128 + bj * 32 + jj];
        }
        __syncthreads();
#pragma unroll
        for (int kk = 0; kk < 8; kk++) {
            float a[8];
            *(float4*)(a)     = *(const float4*)&As[kk][ty * 8];
            *(float4*)(a + 4) = *(const float4*)&As[kk][ty * 8 + 4];
            float b[3][2];
#pragma unroll
            for (int g = 0; g < 3; g++)
                *(float2*)b[g] = *(const float2*)&Bs[kk][g * 32 + tx * 2];
#pragma unroll
            for (int i = 0; i < 8; i++)
#pragma unroll
                for (int g = 0; g < 3; g++) {
                    acc[i][g][0] += a[i] * b[g][0];
                    acc[i][g][1] += a[i] * b[g][1];
                }
        }
        __syncthreads();
    }

    int j0 = bj * 32 + tx * 2;
    float bi0 = b_iou[j0],       bi1 = b_iou[j0 + 1];
    float bo0 = b_iou[128 + j0], bo1 = b_iou[128 + j0 + 1];
    float bu0 = b_iou[256 + j0], bu1 = b_iou[256 + j0 + 1];
    float bc0 = b_c[j0],         bc1 = b_c[j0 + 1];
#pragma unroll
    for (int i = 0; i < 8; i++) {
        int m = bm * 128 + ty * 8 + i;
        if (m >= n) continue;
        float iv0 = acc[i][0][0] + bi0, iv1 = acc[i][0][1] + bi1;
        float ov0 = acc[i][1][0] + bo0, ov1 = acc[i][1][1] + bo1;
        float uv0 = acc[i][2][0] + bu0, uv1 = acc[i][2][1] + bu1;
        float cv0 = (1.f / (1.f + expf(-iv0))) * tanhf(uv0) + bc0;
        float cv1 = (1.f / (1.f + expf(-iv1))) * tanhf(uv1) + bc1;
        float hv0 = (1.f / (1.f + expf(-ov0))) * tanhf(cv0);
        float hv1 = (1.f / (1.f + expf(-ov1))) * tanhf(cv1);
        *(float2*)&g_c[(size_t)m * 128 + j0]  = make_float2(cv0, cv1);
        *(float2*)&hout[(size_t)m * 128 + j0] = make_float2(hv0, hv1);
    }
}

// ---------------- per-iteration: mattering edges (grid-stride) ----------------
// f = sigmoid(forest[p]@W_f + b_f + h[c]@U_f); accumulate child h and f*c into parent slot.
__global__ void __launch_bounds__(128) k_edge(
    const float* __restrict__ forest, const float* __restrict__ hbuf,
    const float* __restrict__ W_f, const float* __restrict__ b_f,
    const float* __restrict__ U_f, int t)
{
    __shared__ float sf[128], sh[128];
    int lo = g_eoff[t], hi = g_eoff[t + 1];
    int j = threadIdx.x;
    for (int idx = lo + blockIdx.x; idx < hi; idx += gridDim.x) {
        int p = g_ep[idx], ch = g_ec[idx], slot = g_es[idx];
        int xi = g_xslot[p];
        sf[j] = forest[(size_t)p * 128 + j];
        sh[j] = hbuf[(size_t)ch * 128 + j];
        __syncthreads();
        float acc = b_f[j];
#pragma unroll 8
        for (int k = 0; k < 128; k++) acc += sf[k] * W_f[k * 128 + j];
#pragma unroll 8
        for (int k = 0; k < 128; k++) acc += sh[k] * U_f[k * 128 + j];
        float f = 1.f / (1.f + expf(-acc));
        float fc = f * g_c[(size_t)ch * 128 + j];
        atomicAdd(&g_xh[(size_t)xi * 384 + slot * 128 + j], sh[j]);
        atomicAdd(&g_xfc[(size_t)xi * 384 + slot * 128 + j], fc);
        __syncthreads();
    }
}

// ---------------- per-iteration: has-input nodes (grid-stride, full recompute) ----------------
__global__ void __launch_bounds__(128) k_node(
    const float* __restrict__ forest, const float* __restrict__ W_iou,
    const float* __restrict__ b_iou, const float* __restrict__ U_iou,
    const float* __restrict__ W_c, const float* __restrict__ b_c,
    float* __restrict__ hbuf, int t)
{
    __shared__ float xin[512], yin[384];
    int lo = g_noff[t], hi = g_noff[t + 1];
    int j = threadIdx.x;
    for (int pos = lo + blockIdx.x; pos < hi; pos += gridDim.x) {
        int i = g_mnode[pos];
        int xi = g_xslot[i];
        xin[j] = forest[(size_t)i * 128 + j];
#pragma unroll
        for (int s = 0; s < 3; s++) {
            xin[128 + s * 128 + j] = g_xh[(size_t)xi * 384 + s * 128 + j];
            yin[s * 128 + j]       = g_xfc[(size_t)xi * 384 + s * 128 + j];
            g_xh[(size_t)xi * 384 + s * 128 + j] = 0.f;   // self-clean for next replay
            g_xfc[(size_t)xi * 384 + s * 128 + j] = 0.f;
        }
        __syncthreads();
        float aI = b_iou[j], aO = b_iou[128 + j], aU = b_iou[256 + j];
#pragma unroll 4
        for (int k = 0; k < 128; k++) {
            float v = xin[k];
            aI += v * W_iou[k * 384 + j];
            aO += v * W_iou[k * 384 + 128 + j];
            aU += v * W_iou[k * 384 + 256 + j];
        }
#pragma unroll 4
        for (int k = 0; k < 384; k++) {
            float v = xin[128 + k];
            aI += v * U_iou[k * 384 + j];
            aO += v * U_iou[k * 384 + 128 + j];
            aU += v * U_iou[k * 384 + 256 + j];
        }
        float aC = b_c[j];
#pragma unroll 4
        for (int k = 0; k < 384; k++) aC += yin[k] * W_c[k * 128 + j];
        float cv = (1.f / (1.f + expf(-aI))) * tanhf(aU) + aC;
        float hv = (1.f / (1.f + expf(-aO))) * tanhf(cv);
        g_c[(size_t)i * 128 + j] = cv;
        hbuf[(size_t)i * 128 + j] = hv;
        __syncthreads();
    }
}

// ---------------- launch ----------------
extern "C" void kernel_launch(void* const* d_in, const int* in_sizes, int n_in,
                              void* d_out, int out_size) {
    const float* forest = (const float*)d_in[0];
    const int*   adj    = (const int*)d_in[1];
    const int*   no     = (const int*)d_in[2];
    const int*   eo     = (const int*)d_in[3];
    const float* W_iou  = (const float*)d_in[4];
    const float* b_iou  = (const float*)d_in[5];
    const float* U_iou  = (const float*)d_in[6];
    const float* W_c    = (const float*)d_in[7];
    const float* b_c    = (const float*)d_in[8];
    const float* W_f    = (const float*)d_in[9];
    const float* b_f    = (const float*)d_in[10];
    const float* U_f    = (const float*)d_in[11];
    float* hout = (float*)d_out;

    int n = in_sizes[0] / 128;
    int e = in_sizes[1] / 3;

    int ginit = (n + 255) / 256; if (ginit < 1) ginit = 1;
    k_init<<<ginit, 256>>>(n);
    k_count<<<(e + 255) / 256, 256>>>(adj, no, eo, n, e);
    k_scan<<<1, 32>>>();
    k_node_scatter<<<(n + 255) / 256, 256>>>(no, n);
    k_edge_scatter<<<(e + 255) / 256, 256>>>(adj, no, eo, n, e);

    dim3 g5((n + 127) / 128, 4);
    k_simple<<<g5, 256>>>(forest, W_iou, b_iou, b_c, hout, n);

    for (int t = 0; t < ITERS_T; t++) {
        k_edge<<<192, 128>>>(forest, hout, W_f, b_f, U_f, t);
        k_node<<<160, 128>>>(forest, W_iou, b_iou, U_iou, W_c, b_c, hout, t);
    }
}

// round 6
// speedup vs baseline: 1.0298x; 1.0298x over previous
#include <cuda_runtime.h>
#include <math.h>

#define NMAX 150000
#define EMAX 150000
#define ITERS_T 31
#define HMAX 65536

// ---------------- device scratch (static allocations only) ----------------
__device__ float g_c[NMAX * 128];       // cell state c (h lives in d_out)
__device__ float g_xh[HMAX * 384];      // per-has-input-node child_h accum (zero-init, self-cleaning)
__device__ float g_xfc[HMAX * 384];     // per-has-input-node f*c accum
__device__ int g_mnode[NMAX];           // has-input node ids, grouped by iteration
__device__ int g_xslot[NMAX];           // node -> dense accumulation slot
__device__ int g_hasin[NMAX];
__device__ int g_ep[EMAX], g_ec[EMAX], g_es[EMAX];   // mattering edges grouped by iter
__device__ int g_ecnt[ITERS_T + 1], g_ncnt[ITERS_T + 1];
__device__ int g_eoff[ITERS_T + 2], g_noff[ITERS_T + 2];
__device__ int g_ecur[ITERS_T + 1], g_ncur[ITERS_T + 1];

// ---------------- prep ----------------
__global__ void k_init(int n) {
    int i = blockIdx.x * blockDim.x + threadIdx.x;
    if (i < n) g_hasin[i] = 0;
    if (i <= ITERS_T) { g_ecnt[i] = 0; g_ncnt[i] = 0; g_ecur[i] = 0; g_ncur[i] = 0; }
}

// NOTE: adjacency / node_order / edge_order arrive as int32 (JAX x64 disabled).
__device__ __forceinline__ bool edge_matters(
    const int* __restrict__ adj, const int* __restrict__ no,
    const int* __restrict__ eo, int n, int i,
    int& sp, int& sc, int& slot, int& ti)
{
    int p = adj[3 * i], c = adj[3 * i + 1];
    if (!(p >= 0 && p < n && c >= 0 && c < n)) return false;   // valid
    int t = eo[i];
    if (t < 0 || t >= ITERS_T) return false;
    sp = p; sc = c;
    if (no[sp] != t) return false;       // parent must update at this iteration
    if (!(no[sc] < t)) return false;     // child h/c still zero otherwise -> no-op
    int s = adj[3 * i + 2] + 1;
    slot = s < 0 ? 0 : (s > 2 ? 2 : s);
    ti = t;
    return true;
}

__global__ void k_count(const int* __restrict__ adj, const int* __restrict__ no,
                        const int* __restrict__ eo, int n, int e) {
    int i = blockIdx.x * blockDim.x + threadIdx.x;
    if (i >= e) return;
    int sp, sc, slot, ti;
    if (!edge_matters(adj, no, eo, n, i, sp, sc, slot, ti)) return;
    atomicAdd(&g_ecnt[ti], 1);
    if (atomicExch(&g_hasin[sp], 1) == 0) atomicAdd(&g_ncnt[ti], 1);
}

__global__ void k_scan() {
    if (threadIdx.x == 0 && blockIdx.x == 0) {
        int se = 0, sn = 0;
        for (int t = 0; t < ITERS_T; t++) {
            g_eoff[t] = se; se += g_ecnt[t];
            g_noff[t] = sn; sn += g_ncnt[t];
        }
        g_eoff[ITERS_T] = se; g_noff[ITERS_T] = sn;
    }
}

__global__ void k_node_scatter(const int* __restrict__ no, int n) {
    int i = blockIdx.x * blockDim.x + threadIdx.x;
    if (i >= n) return;
    if (!g_hasin[i]) return;
    int t = no[i];
    if (t < 0 || t >= ITERS_T) return;
    int pos = g_noff[t] + atomicAdd(&g_ncur[t], 1);
    g_mnode[pos] = i;
    g_xslot[i] = pos < HMAX ? pos : HMAX - 1;
}

__global__ void k_edge_scatter(const int* __restrict__ adj, const int* __restrict__ no,
                               const int* __restrict__ eo, int n, int e) {
    int i = blockIdx.x * blockDim.x + threadIdx.x;
    if (i >= e) return;
    int sp, sc, slot, ti;
    if (!edge_matters(adj, no, eo, n, i, sp, sc, slot, ti)) return;
    int pos = g_eoff[ti] + atomicAdd(&g_ecur[ti], 1);
    g_ep[pos] = sp; g_ec[pos] = sc; g_es[pos] = slot;
}

// ---------------- simple pass v2: register-tiled SGEMM + fused epilogue --------------
// Block tile: M=128 nodes, 32 cols of each of 3 gates (N_eff=96), K=128 in 16 chunks of 8.
// 256 threads; each thread computes 8 rows x (3 gates x 2 cols) = 48 outputs.
// iou = forest @ W_iou + b_iou ; c = sig(i)*tanh(u) + b_c ; h = sig(o)*tanh(c)
__global__ void __launch_bounds__(256) k_simple(
    const float* __restrict__ forest, const float* __restrict__ W_iou,
    const float* __restrict__ b_iou, const float* __restrict__ b_c,
    float* __restrict__ hout, int n)
{
    __shared__ float As[8][132];     // transposed A chunk, padded row
    __shared__ float Bs[8][96];      // [k][g*32+jj]
    int tid = threadIdx.x;
    int bm = blockIdx.x, bj = blockIdx.y;
    int tx = tid & 15;               // 2 cols per gate: jj = tx*2
    int ty = tid >> 4;               // 8 rows: m = ty*8 + i

    // A load mapping: each thread one float4
    int arow = tid >> 1;
    int acol = (tid & 1) * 4;
    int grow = bm * 128 + arow; if (grow >= n) grow = n - 1;
    const float* aptr = forest + (size_t)grow * 128 + acol;

    float acc[8][3][2];
#pragma unroll
    for (int i = 0; i < 8; i++)
#pragma unroll
        for (int g = 0; g < 3; g++) { acc[i][g][0] = 0.f; acc[i][g][1] = 0.f; }

    for (int kc = 0; kc < 16; kc++) {
        float4 av = *(const float4*)(aptr + kc * 8);
        As[acol + 0][arow] = av.x;
        As[acol + 1][arow] = av.y;
        As[acol + 2][arow] = av.z;
        As[acol + 3][arow] = av.w;
#pragma unroll
        for (int s = 0; s < 3; s++) {
            int idx = s * 256 + tid;           // 0..767 covers 8x96
            int kk = idx / 96, c = idx - kk * 96;
            int g = c >> 5, jj = c & 31;
            Bs[kk][c] = W_iou[(kc * 8 + kk) * 384 + g * 128 + bj * 32 + jj];
        }
        __syncthreads();
#pragma unroll
        for (int kk = 0; kk < 8; kk++) {
            float a[8];
            *(float4*)(a)     = *(const float4*)&As[kk][ty * 8];
            *(float4*)(a + 4) = *(const float4*)&As[kk][ty * 8 + 4];
            float b[3][2];
#pragma unroll
            for (int g = 0; g < 3; g++)
                *(float2*)b[g] = *(const float2*)&Bs[kk][g * 32 + tx * 2];
#pragma unroll
            for (int i = 0; i < 8; i++)
#pragma unroll
                for (int g = 0; g < 3; g++) {
                    acc[i][g][0] += a[i] * b[g][0];
                    acc[i][g][1] += a[i] * b[g][1];
                }
        }
        __syncthreads();
    }

    int j0 = bj * 32 + tx * 2;
    float bi0 = b_iou[j0],       bi1 = b_iou[j0 + 1];
    float bo0 = b_iou[128 + j0], bo1 = b_iou[128 + j0 + 1];
    float bu0 = b_iou[256 + j0], bu1 = b_iou[256 + j0 + 1];
    float bc0 = b_c[j0],         bc1 = b_c[j0 + 1];
#pragma unroll
    for (int i = 0; i < 8; i++) {
        int m = bm * 128 + ty * 8 + i;
        if (m >= n) continue;
        float iv0 = acc[i][0][0] + bi0, iv1 = acc[i][0][1] + bi1;
        float ov0 = acc[i][1][0] + bo0, ov1 = acc[i][1][1] + bo1;
        float uv0 = acc[i][2][0] + bu0, uv1 = acc[i][2][1] + bu1;
        float cv0 = (1.f / (1.f + expf(-iv0))) * tanhf(uv0) + bc0;
        float cv1 = (1.f / (1.f + expf(-iv1))) * tanhf(uv1) + bc1;
        float hv0 = (1.f / (1.f + expf(-ov0))) * tanhf(cv0);
        float hv1 = (1.f / (1.f + expf(-ov1))) * tanhf(cv1);
        *(float2*)&g_c[(size_t)m * 128 + j0]  = make_float2(cv0, cv1);
        *(float2*)&hout[(size_t)m * 128 + j0] = make_float2(hv0, hv1);
    }
}

// ---------------- per-iteration: mattering edges (grid-stride) ----------------
// f = sigmoid(forest[p]@W_f + b_f + h[c]@U_f); accumulate child h and f*c into parent slot.
__global__ void __launch_bounds__(128) k_edge(
    const float* __restrict__ forest, const float* __restrict__ hbuf,
    const float* __restrict__ W_f, const float* __restrict__ b_f,
    const float* __restrict__ U_f, int t)
{
    __shared__ float sf[128], sh[128];
    int lo = g_eoff[t], hi = g_eoff[t + 1];
    int j = threadIdx.x;
    for (int idx = lo + blockIdx.x; idx < hi; idx += gridDim.x) {
        int p = g_ep[idx], ch = g_ec[idx], slot = g_es[idx];
        int xi = g_xslot[p];
        sf[j] = forest[(size_t)p * 128 + j];
        sh[j] = hbuf[(size_t)ch * 128 + j];
        __syncthreads();
        float acc = b_f[j];
#pragma unroll 8
        for (int k = 0; k < 128; k++) acc += sf[k] * W_f[k * 128 + j];
#pragma unroll 8
        for (int k = 0; k < 128; k++) acc += sh[k] * U_f[k * 128 + j];
        float f = 1.f / (1.f + expf(-acc));
        float fc = f * g_c[(size_t)ch * 128 + j];
        atomicAdd(&g_xh[(size_t)xi * 384 + slot * 128 + j], sh[j]);
        atomicAdd(&g_xfc[(size_t)xi * 384 + slot * 128 + j], fc);
        __syncthreads();
    }
}

// ---------------- per-iteration: has-input nodes (grid-stride, full recompute) ----------------
__global__ void __launch_bounds__(128) k_node(
    const float* __restrict__ forest, const float* __restrict__ W_iou,
    const float* __restrict__ b_iou, const float* __restrict__ U_iou,
    const float* __restrict__ W_c, const float* __restrict__ b_c,
    float* __restrict__ hbuf, int t)
{
    __shared__ float xin[512], yin[384];
    int lo = g_noff[t], hi = g_noff[t + 1];
    int j = threadIdx.x;
    for (int pos = lo + blockIdx.x; pos < hi; pos += gridDim.x) {
        int i = g_mnode[pos];
        int xi = g_xslot[i];
        xin[j] = forest[(size_t)i * 128 + j];
#pragma unroll
        for (int s = 0; s < 3; s++) {
            xin[128 + s * 128 + j] = g_xh[(size_t)xi * 384 + s * 128 + j];
            yin[s * 128 + j]       = g_xfc[(size_t)xi * 384 + s * 128 + j];
            g_xh[(size_t)xi * 384 + s * 128 + j] = 0.f;   // self-clean for next replay
            g_xfc[(size_t)xi * 384 + s * 128 + j] = 0.f;
        }
        __syncthreads();
        float aI = b_iou[j], aO = b_iou[128 + j], aU = b_iou[256 + j];
#pragma unroll 4
        for (int k = 0; k < 128; k++) {
            float v = xin[k];
            aI += v * W_iou[k * 384 + j];
            aO += v * W_iou[k * 384 + 128 + j];
            aU += v * W_iou[k * 384 + 256 + j];
        }
#pragma unroll 4
        for (int k = 0; k < 384; k++) {
            float v = xin[128 + k];
            aI += v * U_iou[k * 384 + j];
            aO += v * U_iou[k * 384 + 128 + j];
            aU += v * U_iou[k * 384 + 256 + j];
        }
        float aC = b_c[j];
#pragma unroll 4
        for (int k = 0; k < 384; k++) aC += yin[k] * W_c[k * 128 + j];
        float cv = (1.f / (1.f + expf(-aI))) * tanhf(aU) + aC;
        float hv = (1.f / (1.f + expf(-aO))) * tanhf(cv);
        g_c[(size_t)i * 128 + j] = cv;
        hbuf[(size_t)i * 128 + j] = hv;
        __syncthreads();
    }
}

// ---------------- launch ----------------
extern "C" void kernel_launch(void* const* d_in, const int* in_sizes, int n_in,
                              void* d_out, int out_size) {
    const float* forest = (const float*)d_in[0];
    const int*   adj    = (const int*)d_in[1];
    const int*   no     = (const int*)d_in[2];
    const int*   eo     = (const int*)d_in[3];
    const float* W_iou  = (const float*)d_in[4];
    const float* b_iou  = (const float*)d_in[5];
    const float* U_iou  = (const float*)d_in[6];
    const float* W_c    = (const float*)d_in[7];
    const float* b_c    = (const float*)d_in[8];
    const float* W_f    = (const float*)d_in[9];
    const float* b_f    = (const float*)d_in[10];
    const float* U_f    = (const float*)d_in[11];
    float* hout = (float*)d_out;

    int n = in_sizes[0] / 128;
    int e = in_sizes[1] / 3;

    int ginit = (n + 255) / 256; if (ginit < 1) ginit = 1;
    k_init<<<ginit, 256>>>(n);
    k_count<<<(e + 255) / 256, 256>>>(adj, no, eo, n, e);
    k_scan<<<1, 32>>>();
    k_node_scatter<<<(n + 255) / 256, 256>>>(no, n);
    k_edge_scatter<<<(e + 255) / 256, 256>>>(adj, no, eo, n, e);

    dim3 g5((n + 127) / 128, 4);
    k_simple<<<g5, 256>>>(forest, W_iou, b_iou, b_c, hout, n);

    for (int t = 0; t < ITERS_T; t++) {
        k_edge<<<192, 128>>>(forest, hout, W_f, b_f, U_f, t);
        k_node<<<160, 128>>>(forest, W_iou, b_iou, U_iou, W_c, b_c, hout, t);
    }
}